// round 4
// baseline (speedup 1.0000x reference)
#include <cuda_runtime.h>

#define NC 4096
#define NA 2048
#define NB (NC + NA)          // 6144 bodies
#define TPB 256
#define CHUNK 256
#define NXB (NB / TPB)        // 24 body tiles
#define NCY (NC / CHUNK)      // 16 circle j-chunks
#define NAY (NA / CHUNK)      // 8 aabb j-chunks
#define NYB (NCY + NAY)       // 24 j-chunks
#define EPSF 1e-9f

// partial corrections: [NYB][NB*2]
__device__ float g_partial[NYB * NB * 2];

__device__ __forceinline__ float rsq_approx(float x) {
    float r;
    asm("rsqrt.approx.f32 %0, %1;" : "=f"(r) : "f"(x));
    return r;
}

__global__ void __launch_bounds__(TPB)
collide_kernel(const float* __restrict__ cpos, const float* __restrict__ crad,
               const float* __restrict__ apos, const float* __restrict__ ahalf)
{
    __shared__ float4 sj[CHUNK];   // (x, y, r_or_hx, hy)

    const int i  = blockIdx.x * TPB + threadIdx.x;   // body index 0..NB-1
    const bool i_is_circle = (i < NC);
    const int jy = blockIdx.y;
    const bool j_is_circle = (jy < NCY);
    const int j0 = j_is_circle ? (jy * CHUNK) : ((jy - NCY) * CHUNK);

    // cooperative smem stage (CHUNK == TPB: one element per thread)
    {
        const int t = threadIdx.x;
        if (j_is_circle) {
            float2 p = ((const float2*)cpos)[j0 + t];
            sj[t] = make_float4(p.x, p.y, crad[j0 + t], 0.0f);
        } else {
            float2 p = ((const float2*)apos)[j0 + t];
            float2 h = ((const float2*)ahalf)[j0 + t];
            sj[t] = make_float4(p.x, p.y, h.x, h.y);
        }
    }
    __syncthreads();

    float cx = 0.0f, cy = 0.0f;

    if (i_is_circle) {
        const float2 pi = ((const float2*)cpos)[i];
        const float  ri = crad[i];
        const float  ri2 = ri * ri;
        if (j_is_circle) {
            // circle vs circle
            #pragma unroll 4
            for (int k = 0; k < CHUNK; k++) {
                float4 b = sj[k];
                float dx = pi.x - b.x;
                float dy = pi.y - b.y;
                float d2 = fmaf(dx, dx, dy * dy);
                float rsum = ri + b.z;
                float inv = rsq_approx(d2);
                float s = fmaf(0.5f * rsum, inv, -0.5f);   // 0.5*(rsum-dist)/dist
                bool hit = (d2 > EPSF) && (d2 < rsum * rsum);
                s = hit ? s : 0.0f;
                cx = fmaf(s, dx, cx);
                cy = fmaf(s, dy, cy);
            }
        } else {
            // circle vs aabb (push on circle)
            #pragma unroll 4
            for (int k = 0; k < CHUNK; k++) {
                float4 b = sj[k];
                float relx = pi.x - b.x;
                float rely = pi.y - b.y;
                float qx = fminf(fmaxf(relx, -b.z), b.z);
                float qy = fminf(fmaxf(rely, -b.w), b.w);
                float dx = relx - qx;
                float dy = rely - qy;
                float dd2 = fmaf(dx, dx, dy * dy);
                float inv = rsq_approx(dd2);
                float s = fmaf(0.5f * ri, inv, -0.5f);
                bool hit = (dd2 > EPSF) && (dd2 < ri2);
                s = hit ? s : 0.0f;
                cx = fmaf(s, dx, cx);
                cy = fmaf(s, dy, cy);
            }
        }
    } else {
        const int ia = i - NC;
        const float2 pi = ((const float2*)apos)[ia];
        const float2 hi = ((const float2*)ahalf)[ia];
        if (j_is_circle) {
            // aabb vs circle (equal-and-opposite push on aabb)
            #pragma unroll 4
            for (int k = 0; k < CHUNK; k++) {
                float4 b = sj[k];
                float relx = b.x - pi.x;          // circle - aabb
                float rely = b.y - pi.y;
                float qx = fminf(fmaxf(relx, -hi.x), hi.x);
                float qy = fminf(fmaxf(rely, -hi.y), hi.y);
                float dx = relx - qx;
                float dy = rely - qy;
                float dd2 = fmaf(dx, dx, dy * dy);
                float rj = b.z;
                float inv = rsq_approx(dd2);
                float s = fmaf(0.5f * rj, inv, -0.5f);
                bool hit = (dd2 > EPSF) && (dd2 < rj * rj);
                s = hit ? -s : 0.0f;              // negated: push on the box
                cx = fmaf(s, dx, cx);
                cy = fmaf(s, dy, cy);
            }
        } else {
            // aabb vs aabb
            #pragma unroll 4
            for (int k = 0; k < CHUNK; k++) {
                float4 b = sj[k];
                int j = j0 + k;
                float dax = pi.x - b.x;
                float day = pi.y - b.y;
                float ovx = (hi.x + b.z) - fabsf(dax);
                float ovy = (hi.y + b.w) - fabsf(day);
                bool hit = (ovx > 0.0f) && (ovy > 0.0f) && (ia != j);
                bool usex = (ovx <= ovy);
                float px = copysignf(0.5f * ovx, dax);   // sgn(+0)=+1 matches da>=0 rule
                float py = copysignf(0.5f * ovy, day);
                cx += (hit && usex)  ? px : 0.0f;
                cy += (hit && !usex) ? py : 0.0f;
            }
        }
    }

    float* part = &g_partial[(size_t)jy * (NB * 2)];
    part[2 * i + 0] = cx;
    part[2 * i + 1] = cy;
}

__global__ void __launch_bounds__(TPB)
reduce_kernel(const float* __restrict__ cpos, const float* __restrict__ apos,
              float* __restrict__ out)
{
    const int idx = blockIdx.x * TPB + threadIdx.x;   // 0 .. NB*2-1
    if (idx >= NB * 2) return;
    float base = (idx < 2 * NC) ? cpos[idx] : apos[idx - 2 * NC];
    float acc = 0.0f;
    #pragma unroll
    for (int y = 0; y < NYB; y++) {
        acc += g_partial[(size_t)y * (NB * 2) + idx];
    }
    out[idx] = base + acc;
}

extern "C" void kernel_launch(void* const* d_in, const int* in_sizes, int n_in,
                              void* d_out, int out_size)
{
    const float* cpos  = (const float*)d_in[0];   // [4096,2]
    const float* crad  = (const float*)d_in[1];   // [4096]
    const float* apos  = (const float*)d_in[2];   // [2048,2]
    const float* ahalf = (const float*)d_in[3];   // [2048,2]
    float* out = (float*)d_out;                   // [6144,2]

    dim3 grid(NXB, NYB);
    collide_kernel<<<grid, TPB>>>(cpos, crad, apos, ahalf);
    reduce_kernel<<<(NB * 2 + TPB - 1) / TPB, TPB>>>(cpos, apos, out);
}